// round 16
// baseline (speedup 1.0000x reference)
#include <cuda_runtime.h>
#include <cuda_bf16.h>
#include <stdint.h>

// SparseMixerV2 forward — warp-private TRIPLE-buffered cp.async pipelines.
//   sel = argmax(logits) (first occurrence)
//   keep_j iff l_j >= T,  T = m*0.8 (m>=0) else m*1.25  [exact mask closed form]
//   multiplier = (0.3333+0.6667) / sum_keep exp(l_j - m)
// rand_u provably dead (sel == argmax(masked_gates) always).
//
// One warp per block, one row per lane, 32-row / 8KB tiles, 3-deep ring in
// static smem (24KB) -> 9 blocks/SM but 2 outstanding tiles per warp
// (144KB in flight per SM vs 96KB at depth 2). XOR swizzle write via
// cp.async + XOR-rotated LDS.128 read (self-de-swizzling, conflict-free).

#define E 64
#define TPB 32
#define TILE 32
#define BUF_FLOATS (TILE * E)          // 2048 floats = 8KB
#define BUF_BYTES  (BUF_FLOATS * 4)
#define LOG2E 1.4426950408889634f

__device__ __forceinline__ void prefetch_tile(const float* __restrict__ logits,
                                              float* __restrict__ buf,
                                              int tile, int lane)
{
    const float4* g = reinterpret_cast<const float4*>(logits + (size_t)tile * TILE * E);
    #pragma unroll
    for (int i = 0; i < 16; i++) {
        int idx  = lane + i * 32;
        int row  = idx >> 4;
        int col  = idx & 15;
        int slot = col ^ (row & 15);       // XOR swizzle
        uint32_t dst = (uint32_t)__cvta_generic_to_shared(buf + row * E + slot * 4);
        asm volatile("cp.async.cg.shared.global [%0], [%1], 16;"
                     :: "r"(dst), "l"(g + idx) : "memory");
    }
    asm volatile("cp.async.commit_group;" ::: "memory");
}

__global__ void __launch_bounds__(TPB)
sparsemixer_d3(const float* __restrict__ logits,
               float* __restrict__ out,      // [0,N): sel, [N,2N): mult, [2N]: 0
               int N, int out_size)
{
    __shared__ float smem[3 * BUF_FLOATS];     // 24KB static, 3-slot ring
    const int t = threadIdx.x;

    if (blockIdx.x == 0 && t == 0 && out_size > 2 * N)
        out[2 * N] = 0.0f;                     // balance_loss

    const int numTiles = N / TILE;
    const int g = gridDim.x;
    int tile = blockIdx.x;
    if (tile >= numTiles) return;

    // prologue: fill slots 0 and 1
    prefetch_tile(logits, smem, tile, t);
    if (tile + g < numTiles)
        prefetch_tile(logits, smem + BUF_FLOATS, tile + g, t);

    const uint32_t sbase = (uint32_t)__cvta_generic_to_shared(smem);
    const uint32_t rowrot0 = sbase + (uint32_t)t * 256u + ((uint32_t)(t & 15) << 4);

    int bufIdx = 0;
    for (; tile < numTiles; tile += g) {
        const bool has1 = (tile + g)     < numTiles;
        const bool has2 = (tile + 2 * g) < numTiles;
        if (has2) {
            const int pf = (bufIdx == 0) ? 2 : (bufIdx - 1);   // (bufIdx+2)%3
            prefetch_tile(logits, smem + pf * BUF_FLOATS, tile + 2 * g, t);
            asm volatile("cp.async.wait_group 2;" ::: "memory");
        } else if (has1) {
            asm volatile("cp.async.wait_group 1;" ::: "memory");
        } else {
            asm volatile("cp.async.wait_group 0;" ::: "memory");
        }
        __syncwarp();

        // ---- gather my row: 16 LDS.128 (XOR address self-de-swizzles) ----
        float4 v[16];
        const uint32_t rb = rowrot0 + (uint32_t)bufIdx * BUF_BYTES;
        #pragma unroll
        for (int c = 0; c < 16; c++) {
            float4 tmp;
            asm volatile("ld.shared.v4.f32 {%0,%1,%2,%3}, [%4];"
                         : "=f"(tmp.x), "=f"(tmp.y), "=f"(tmp.z), "=f"(tmp.w)
                         : "r"(rb ^ ((uint32_t)c << 4)));
            v[c] = tmp;
        }

        // ---- pass 1: per-quad maxes, then row max ----
        float qm[16];
        #pragma unroll
        for (int c = 0; c < 16; c++)
            qm[c] = fmaxf(fmaxf(v[c].x, v[c].y), fmaxf(v[c].z, v[c].w));
        float a0 = fmaxf(fmaxf(qm[0], qm[1]),  fmaxf(qm[2],  qm[3]));
        float a1 = fmaxf(fmaxf(qm[4], qm[5]),  fmaxf(qm[6],  qm[7]));
        float a2 = fmaxf(fmaxf(qm[8], qm[9]),  fmaxf(qm[10], qm[11]));
        float a3 = fmaxf(fmaxf(qm[12], qm[13]), fmaxf(qm[14], qm[15]));
        const float m = fmaxf(fmaxf(a0, a1), fmaxf(a2, a3));

        const float T  = m * (m >= 0.0f ? 0.8f : 1.25f);   // keep iff x >= T
        const float c0 = -m * LOG2E;                        // exp(l-m)=ex2(l*log2e+c0)

        // ---- pass 2: masked exp-sum (4 inst/element), 2-way split ----
        float sa = 0.0f, sb = 0.0f;
        #define SM_ELEM(S, X) {                                                  \
            const float x_ = (X);                                                \
            float ex_;                                                           \
            asm("ex2.approx.f32 %0, %1;" : "=f"(ex_) : "f"(fmaf(x_, LOG2E, c0)));\
            if (x_ >= T) S += ex_; }
        #pragma unroll
        for (int j = 0; j < 16; j += 2) {
            SM_ELEM(sa, v[j].x)   SM_ELEM(sa, v[j].y)
            SM_ELEM(sa, v[j].z)   SM_ELEM(sa, v[j].w)
            SM_ELEM(sb, v[j+1].x) SM_ELEM(sb, v[j+1].y)
            SM_ELEM(sb, v[j+1].z) SM_ELEM(sb, v[j+1].w)
        }
        #undef SM_ELEM
        const float s = sa + sb;

        // ---- argmax: first quad attaining m (desc scan -> smallest j) ----
        int selq = 0;
        #pragma unroll
        for (int j = 15; j >= 0; j--)
            if (qm[j] == m) selq = j;

        float4 q;                                // re-read winning quad
        asm volatile("ld.shared.v4.f32 {%0,%1,%2,%3}, [%4];"
                     : "=f"(q.x), "=f"(q.y), "=f"(q.z), "=f"(q.w)
                     : "r"(rb ^ ((uint32_t)selq << 4)));
        int e = 3;
        if (q.z == m) e = 2;
        if (q.y == m) e = 1;
        if (q.x == m) e = 0;
        const int sel = 4 * selq + e;

        const int row = tile * TILE + t;
        const float mf1 = 0.3333f + 0.6667f;     // mask_for_one (always true-branch)
        out[row]     = (float)sel;
        out[N + row] = mf1 / s;

        __syncwarp();                            // lanes done reading this slot
        bufIdx = (bufIdx == 2) ? 0 : bufIdx + 1;
    }
}

extern "C" void kernel_launch(void* const* d_in, const int* in_sizes, int n_in,
                              void* d_out, int out_size)
{
    const float* logits = (const float*)d_in[0];   // d_in[1] = rand_u: dead
    float* out = (float*)d_out;

    const int N = in_sizes[0] / E;                 // 1048576
    const int numTiles = N / TILE;                 // 32768

    int blocks = 9 * 148;                          // 9 blocks/SM (24KB smem each)
    if (blocks > numTiles) blocks = numTiles;

    sparsemixer_d3<<<blocks, TPB>>>(logits, out, N, out_size);
}

// round 17
// speedup vs baseline: 1.0805x; 1.0805x over previous
#include <cuda_runtime.h>
#include <cuda_bf16.h>
#include <stdint.h>

// SparseMixerV2 forward — round-13 winner + L2 prefetch hint + streaming stores.
//   sel = argmax(logits) (first occurrence)
//   keep_j iff l_j >= T,  T = m*0.8 (m>=0) else m*1.25  [exact mask closed form]
//   multiplier = (0.3333+0.6667) / sum_keep exp(l_j - m)
// rand_u provably dead (sel == argmax(masked_gates) always).
//
// One warp per block, one row per lane, 32-row / 8KB tiles, 2-deep ring in
// static smem, 12 warp-pipelines/SM (best measured config). cp.async.cg with
// .L2::256B prefetch to improve DRAM row-buffer locality; outputs via
// st.global.cs (evict-first — never re-read).

#define E 64
#define TPB 32
#define TILE 32
#define BUF_FLOATS (TILE * E)          // 2048 floats = 8KB
#define LOG2E 1.4426950408889634f

__device__ __forceinline__ void prefetch_tile(const float* __restrict__ logits,
                                              float* __restrict__ buf,
                                              int tile, int lane)
{
    const float4* g = reinterpret_cast<const float4*>(logits + (size_t)tile * TILE * E);
    #pragma unroll
    for (int i = 0; i < 16; i++) {
        int idx  = lane + i * 32;
        int row  = idx >> 4;
        int col  = idx & 15;
        int slot = col ^ (row & 15);       // XOR swizzle
        uint32_t dst = (uint32_t)__cvta_generic_to_shared(buf + row * E + slot * 4);
        asm volatile("cp.async.cg.shared.global.L2::256B [%0], [%1], 16;"
                     :: "r"(dst), "l"(g + idx) : "memory");
    }
    asm volatile("cp.async.commit_group;" ::: "memory");
}

__global__ void __launch_bounds__(TPB)
sparsemixer_warp(const float* __restrict__ logits,
                 float* __restrict__ out,      // [0,N): sel, [N,2N): mult, [2N]: 0
                 int N, int out_size)
{
    __shared__ float smem[2 * BUF_FLOATS];     // 16KB static
    const int t = threadIdx.x;

    if (blockIdx.x == 0 && t == 0 && out_size > 2 * N)
        out[2 * N] = 0.0f;                     // balance_loss

    const int numTiles = N / TILE;
    int tile = blockIdx.x;
    if (tile >= numTiles) return;

    prefetch_tile(logits, smem, tile, t);      // slot 0

    const uint32_t sbase = (uint32_t)__cvta_generic_to_shared(smem);
    const uint32_t rowrot0 = sbase + (uint32_t)t * 256u + ((uint32_t)(t & 15) << 4);

    int bufIdx = 0;
    for (; tile < numTiles; tile += gridDim.x) {
        const int nextTile = tile + gridDim.x;
        if (nextTile < numTiles) {
            prefetch_tile(logits, smem + (bufIdx ^ 1) * BUF_FLOATS, nextTile, t);
            asm volatile("cp.async.wait_group 1;" ::: "memory");
        } else {
            asm volatile("cp.async.wait_group 0;" ::: "memory");
        }
        __syncwarp();

        // ---- gather my row: 16 LDS.128 (XOR address self-de-swizzles) ----
        float4 v[16];
        const uint32_t rb = rowrot0 + (uint32_t)bufIdx * (BUF_FLOATS * 4u);
        #pragma unroll
        for (int c = 0; c < 16; c++) {
            float4 tmp;
            asm volatile("ld.shared.v4.f32 {%0,%1,%2,%3}, [%4];"
                         : "=f"(tmp.x), "=f"(tmp.y), "=f"(tmp.z), "=f"(tmp.w)
                         : "r"(rb ^ ((uint32_t)c << 4)));
            v[c] = tmp;
        }

        // ---- pass 1: per-quad maxes, then row max ----
        float qm[16];
        #pragma unroll
        for (int c = 0; c < 16; c++)
            qm[c] = fmaxf(fmaxf(v[c].x, v[c].y), fmaxf(v[c].z, v[c].w));
        float a0 = fmaxf(fmaxf(qm[0], qm[1]),  fmaxf(qm[2],  qm[3]));
        float a1 = fmaxf(fmaxf(qm[4], qm[5]),  fmaxf(qm[6],  qm[7]));
        float a2 = fmaxf(fmaxf(qm[8], qm[9]),  fmaxf(qm[10], qm[11]));
        float a3 = fmaxf(fmaxf(qm[12], qm[13]), fmaxf(qm[14], qm[15]));
        const float m = fmaxf(fmaxf(a0, a1), fmaxf(a2, a3));

        // keep iff x >= T  (exact closed form of the jitter mask)
        const float T  = m * (m >= 0.0f ? 0.8f : 1.25f);
        const float c0 = -m * LOG2E;           // exp(l-m) = ex2(l*log2e + c0)

        // ---- pass 2: masked exp-sum only (4 inst/element), 2-way split ----
        float sa = 0.0f, sb = 0.0f;
        #define SM_ELEM(S, X) {                                                  \
            const float x_ = (X);                                                \
            float ex_;                                                           \
            asm("ex2.approx.f32 %0, %1;" : "=f"(ex_) : "f"(fmaf(x_, LOG2E, c0)));\
            if (x_ >= T) S += ex_; }
        #pragma unroll
        for (int j = 0; j < 16; j += 2) {
            SM_ELEM(sa, v[j].x)   SM_ELEM(sa, v[j].y)
            SM_ELEM(sa, v[j].z)   SM_ELEM(sa, v[j].w)
            SM_ELEM(sb, v[j+1].x) SM_ELEM(sb, v[j+1].y)
            SM_ELEM(sb, v[j+1].z) SM_ELEM(sb, v[j+1].w)
        }
        #undef SM_ELEM
        const float s = sa + sb;

        // ---- argmax: first quad attaining m (descending scan -> smallest j) ----
        int selq = 0;
        #pragma unroll
        for (int j = 15; j >= 0; j--)
            if (qm[j] == m) selq = j;

        // re-read winning quad (dynamic XOR address, still conflict-free)
        float4 q;
        asm volatile("ld.shared.v4.f32 {%0,%1,%2,%3}, [%4];"
                     : "=f"(q.x), "=f"(q.y), "=f"(q.z), "=f"(q.w)
                     : "r"(rb ^ ((uint32_t)selq << 4)));
        int e = 3;
        if (q.z == m) e = 2;
        if (q.y == m) e = 1;
        if (q.x == m) e = 0;
        const int sel = 4 * selq + e;

        const int row = tile * TILE + t;
        const float mf1 = 0.3333f + 0.6667f;   // mask_for_one (always true-branch)
        __stcs(&out[row],     (float)sel);     // streaming store: never re-read
        __stcs(&out[N + row], mf1 / s);

        __syncwarp();
        bufIdx ^= 1;
    }
}

extern "C" void kernel_launch(void* const* d_in, const int* in_sizes, int n_in,
                              void* d_out, int out_size)
{
    const float* logits = (const float*)d_in[0];   // d_in[1] = rand_u: dead
    float* out = (float*)d_out;

    const int N = in_sizes[0] / E;                 // 1048576
    const int numTiles = N / TILE;                 // 32768

    int blocks = 12 * 148;                         // 12 warp-pipelines/SM (best cfg)
    if (blocks > numTiles) blocks = numTiles;

    sparsemixer_warp<<<blocks, TPB>>>(logits, out, N, out_size);
}